// round 1
// baseline (speedup 1.0000x reference)
#include <cuda_runtime.h>
#include <cuda_bf16.h>
#include <cstdint>

#define NSTATES 256
#define DDIM    128
#define BATCH   64
#define TLEN    512
#define BT      (BATCH * TLEN)
#define LOG2PI_F 1.8378770664093453f

// ---------------- device scratch (no allocations allowed) ----------------
__device__ __align__(16) float   g_E[BT * NSTATES];          // 32 MB emissions
__device__ __align__(16) __nv_bfloat16 g_Acm[NSTATES * NSTATES]; // softmax(A), COLUMN-major: g_Acm[j*256 + i]
__device__ __align__(16) float   g_logpi[NSTATES];
__device__ __align__(16) float   g_ivT[DDIM * NSTATES];      // ivT[d*256+n] = exp(-log_var[n][d])
__device__ __align__(16) float   g_mivT[DDIM * NSTATES];     // mu*iv, transposed
__device__ __align__(16) float   g_cn[NSTATES];              // sum_d (mu^2*iv + log_var + log2pi)

// ---------------- prep 1: per-(n) param transforms ----------------
// grid 256 (one block per state n), block 128 (one thread per d)
__global__ void k_prep_params(const float* __restrict__ mu,
                              const float* __restrict__ log_var) {
    int n = blockIdx.x;
    int d = threadIdx.x;
    float lv = log_var[n * DDIM + d];
    float iv = __expf(-lv);
    float mv = mu[n * DDIM + d];
    g_ivT [d * NSTATES + n] = iv;
    g_mivT[d * NSTATES + n] = mv * iv;

    float c = fmaf(mv * mv, iv, lv + LOG2PI_F);
    #pragma unroll
    for (int o = 16; o; o >>= 1) c += __shfl_xor_sync(0xffffffffu, c, o);
    __shared__ float red[4];
    if ((d & 31) == 0) red[d >> 5] = c;
    __syncthreads();
    if (d == 0) g_cn[n] = red[0] + red[1] + red[2] + red[3];
}

// ---------------- prep 2: softmax of transition rows + log_softmax priors ----------------
// grid 257: blocks 0..255 handle transition row i; block 256 handles priors + zeroes out
__global__ void k_prep_trans(const float* __restrict__ trans,
                             const float* __restrict__ priors,
                             float* __restrict__ out) {
    __shared__ float red[8];
    int tid = threadIdx.x;
    int blk = blockIdx.x;

    float v = (blk < NSTATES) ? trans[blk * NSTATES + tid] : priors[tid];

    // row max
    float w = v;
    #pragma unroll
    for (int o = 16; o; o >>= 1) w = fmaxf(w, __shfl_xor_sync(0xffffffffu, w, o));
    if ((tid & 31) == 0) red[tid >> 5] = w;
    __syncthreads();
    float m = red[0];
    #pragma unroll
    for (int q = 1; q < 8; q++) m = fmaxf(m, red[q]);
    __syncthreads();

    // row sum of exp
    float ex = __expf(v - m);
    float s = ex;
    #pragma unroll
    for (int o = 16; o; o >>= 1) s += __shfl_xor_sync(0xffffffffu, s, o);
    if ((tid & 31) == 0) red[tid >> 5] = s;
    __syncthreads();
    float S = 0.f;
    #pragma unroll
    for (int q = 0; q < 8; q++) S += red[q];

    if (blk < NSTATES) {
        // softmax prob, stored column-major for the forward kernel
        g_Acm[tid * NSTATES + blk] = __float2bfloat16(ex / S);
    } else {
        g_logpi[tid] = v - m - __logf(S);
        if (tid == 0) out[0] = 0.0f;   // re-zeroed on every (graph) replay
    }
}

// ---------------- emission kernel ----------------
// grid 512, block 256. Each CTA: 64 bt-rows x all 256 states.
// thread: btg = tid/16 (4 bt rows), ng = tid%16 (16 states)
__global__ void __launch_bounds__(256) k_emission(const float* __restrict__ X) {
    __shared__ float xT[DDIM * 68];   // padded transpose: xT[d*68 + btl]
    int tid = threadIdx.x;
    int bt0 = blockIdx.x * 64;

    for (int idx = tid; idx < 64 * DDIM; idx += 256) {
        int btl = idx >> 7, d = idx & 127;
        xT[d * 68 + btl] = X[(bt0 + btl) * DDIM + d];
    }
    __syncthreads();

    int ng  = tid & 15;    // state group: n in [16*ng, 16*ng+16)
    int btg = tid >> 4;    // bt group:    bt in [4*btg, 4*btg+4)

    float acc[64];
    #pragma unroll
    for (int q = 0; q < 64; q++) acc[q] = 0.f;

    for (int d = 0; d < DDIM; d++) {
        float4 xv = *(const float4*)(xT + d * 68 + 4 * btg);
        float xs[4] = {xv.x, xv.y, xv.z, xv.w};
        const float4* ivp = (const float4*)(g_ivT  + d * NSTATES + 16 * ng);
        const float4* mvp = (const float4*)(g_mivT + d * NSTATES + 16 * ng);
        float4 ivv[4], mvv[4];
        #pragma unroll
        for (int c = 0; c < 4; c++) { ivv[c] = ivp[c]; mvv[c] = mvp[c]; }

        #pragma unroll
        for (int q = 0; q < 4; q++) {
            float x = xs[q];
            float z = -0.5f * x;
            #pragma unroll
            for (int c = 0; c < 4; c++) {
                acc[q*16 + c*4 + 0] = fmaf(x, fmaf(z, ivv[c].x, mvv[c].x), acc[q*16 + c*4 + 0]);
                acc[q*16 + c*4 + 1] = fmaf(x, fmaf(z, ivv[c].y, mvv[c].y), acc[q*16 + c*4 + 1]);
                acc[q*16 + c*4 + 2] = fmaf(x, fmaf(z, ivv[c].z, mvv[c].z), acc[q*16 + c*4 + 2]);
                acc[q*16 + c*4 + 3] = fmaf(x, fmaf(z, ivv[c].w, mvv[c].w), acc[q*16 + c*4 + 3]);
            }
        }
    }

    // E = acc - 0.5 * const_n
    #pragma unroll
    for (int q = 0; q < 4; q++) {
        int bt = bt0 + 4 * btg + q;
        #pragma unroll
        for (int c = 0; c < 4; c++) {
            float4 cn4 = ((const float4*)(g_cn + 16 * ng))[c];
            float4 o;
            o.x = fmaf(-0.5f, cn4.x, acc[q*16 + c*4 + 0]);
            o.y = fmaf(-0.5f, cn4.y, acc[q*16 + c*4 + 1]);
            o.z = fmaf(-0.5f, cn4.z, acc[q*16 + c*4 + 2]);
            o.w = fmaf(-0.5f, cn4.w, acc[q*16 + c*4 + 3]);
            ((float4*)(g_E + (size_t)bt * NSTATES + 16 * ng))[c] = o;
        }
    }
}

// ---------------- forward recursion ----------------
// 64 CTAs (one per batch), 256 threads (one per state j).
// A (bf16) cached in smem COLUMN-major with 129-word stride -> conflict-free LDS.32.
// Dynamic smem: 256*129 words A + 256 floats p + 8 floats wred.
#define FWD_SMEM (256*129*4 + 256*4 + 8*4)

__global__ void __launch_bounds__(256) k_forward(float* __restrict__ out) {
    extern __shared__ unsigned char sm[];
    uint32_t* Asm  = (uint32_t*)sm;                       // [j*129 + k] = (A[2k][j], A[2k+1][j]) as bf16x2
    float*    p    = (float*)(sm + 256 * 129 * 4);        // 16B aligned (132096 % 16 == 0)
    float*    wred = p + 256;

    int b   = blockIdx.x;
    int tid = threadIdx.x;

    // load A tile (bf16 col-major pairs) into padded smem
    const uint32_t* Ag = (const uint32_t*)g_Acm;
    for (int idx = tid; idx < 256 * 128; idx += 256) {
        int j = idx >> 7, k = idx & 127;
        Asm[j * 129 + k] = Ag[idx];
    }

    // alpha0 = log_pi + E[b,0,:]
    float a = g_logpi[tid] + g_E[(size_t)b * TLEN * NSTATES + tid];
    __syncthreads();

    const uint32_t* ac = Asm + tid * 129;

    for (int t = 1; t < TLEN; t++) {
        // m = max_i alpha_i
        float v = a;
        #pragma unroll
        for (int o = 16; o; o >>= 1) v = fmaxf(v, __shfl_xor_sync(0xffffffffu, v, o));
        if ((tid & 31) == 0) wred[tid >> 5] = v;
        __syncthreads();                                   // bar1
        float m = wred[0];
        #pragma unroll
        for (int q = 1; q < 8; q++) m = fmaxf(m, wred[q]);

        p[tid] = __expf(a - m);
        __syncthreads();                                   // bar2

        float e = g_E[((size_t)b * TLEN + t) * NSTATES + tid];  // hidden under the matmul

        // s_j = sum_i p_i * A[i][j]   (thread owns column j = tid)
        float accA = 0.f, accB = 0.f;
        #pragma unroll
        for (int k = 0; k < 128; k += 2) {
            float4 pq = *(const float4*)(p + 2 * k);       // broadcast
            uint32_t w0 = ac[k], w1 = ac[k + 1];
            accA = fmaf(pq.x, __uint_as_float(w0 << 16),          accA);
            accB = fmaf(pq.y, __uint_as_float(w0 & 0xffff0000u),  accB);
            accA = fmaf(pq.z, __uint_as_float(w1 << 16),          accA);
            accB = fmaf(pq.w, __uint_as_float(w1 & 0xffff0000u),  accB);
        }
        a = e + m + __logf(accA + accB);
    }

    // final logsumexp over states, then accumulate into out
    __syncthreads();
    float v = a;
    #pragma unroll
    for (int o = 16; o; o >>= 1) v = fmaxf(v, __shfl_xor_sync(0xffffffffu, v, o));
    if ((tid & 31) == 0) wred[tid >> 5] = v;
    __syncthreads();
    float m = wred[0];
    #pragma unroll
    for (int q = 1; q < 8; q++) m = fmaxf(m, wred[q]);

    float ex = __expf(a - m);
    float s = ex;
    #pragma unroll
    for (int o = 16; o; o >>= 1) s += __shfl_xor_sync(0xffffffffu, s, o);
    __syncthreads();                                       // wred max-reads done
    if ((tid & 31) == 0) wred[tid >> 5] = s;
    __syncthreads();
    if (tid == 0) {
        float S = 0.f;
        #pragma unroll
        for (int q = 0; q < 8; q++) S += wred[q];
        atomicAdd(out, m + __logf(S));
    }
}

// ---------------- launch ----------------
extern "C" void kernel_launch(void* const* d_in, const int* in_sizes, int n_in,
                              void* d_out, int out_size) {
    const float* X       = (const float*)d_in[0];  // [64,512,128]
    const float* mu      = (const float*)d_in[1];  // [256,128]
    const float* log_var = (const float*)d_in[2];  // [256,128]
    const float* trans   = (const float*)d_in[3];  // [256,256]
    const float* priors  = (const float*)d_in[4];  // [256]
    float* out = (float*)d_out;

    cudaFuncSetAttribute(k_forward, cudaFuncAttributeMaxDynamicSharedMemorySize, FWD_SMEM);

    k_prep_params<<<NSTATES, DDIM>>>(mu, log_var);
    k_prep_trans <<<NSTATES + 1, NSTATES>>>(trans, priors, out);
    k_emission   <<<BT / 64, 256>>>(X);
    k_forward    <<<BATCH, 256, FWD_SMEM>>>(out);
}